// round 3
// baseline (speedup 1.0000x reference)
#include <cuda_runtime.h>
#include <cuda_bf16.h>

// HierarchicalSoftmax: mean over B samples of sum over D=17 path nodes of
// BCE-with-logits( W[node]·emb + b[node], dir ).
//
// Inputs (metadata order):
//   d_in[0]: embeddings float32 [B, E]   (B=16384, E=128)
//   d_in[1]: word_idx   int32   [B]
//   d_in[2]: W          float32 [V-1, E] (V=131072)
//   d_in[3]: b          float32 [V-1]
// Output: float32 scalar.

#define HS_D 17            // tree depth = log2(V); fixed for this problem shape
#define HS_E4 32           // E/4 = float4 slices per row
#define WARPS_PER_BLOCK 8
#define MAX_BLOCKS 8192

__device__ float g_hs_partials[MAX_BLOCKS];

__global__ __launch_bounds__(WARPS_PER_BLOCK * 32)
void hs_main_kernel(const float* __restrict__ emb,
                    const int*   __restrict__ word_idx,
                    const float4* __restrict__ W4,
                    const float* __restrict__ bias,
                    int B, int Vm1)
{
    const int warp = blockIdx.x * WARPS_PER_BLOCK + (threadIdx.x >> 5);
    const int lane = threadIdx.x & 31;

    float acc = 0.0f;

    if (warp < B) {
        // Each lane owns 4 consecutive embedding elements: fully coalesced 512B load.
        const float4 e = reinterpret_cast<const float4*>(emb)[warp * HS_E4 + lane];

        // Precompute the full leaf->root path so the 17 W-row loads are
        // independent and can be batched by ptxas (MLP hides L2/DRAM latency).
        int node = word_idx[warp] + Vm1;   // leaf heap index
        int nodes[HS_D];
        unsigned dirs = 0u;
        #pragma unroll
        for (int d = 0; d < HS_D; ++d) {
            dirs |= (unsigned)(node & 1) << d;   // 1 iff came from left child
            node = (node - 1) >> 1;              // parent
            nodes[d] = node;
        }

        #pragma unroll
        for (int d = 0; d < HS_D; ++d) {
            const int n = nodes[d];
            // 32 lanes x float4 = one contiguous 512B row of W: 4 full sectors/lines.
            const float4 w = __ldg(&W4[n * HS_E4 + lane]);
            float p = w.x * e.x + w.y * e.y + w.z * e.z + w.w * e.w;

            // Butterfly reduce: every lane ends with the full dot product.
            p += __shfl_xor_sync(0xffffffffu, p, 16);
            p += __shfl_xor_sync(0xffffffffu, p, 8);
            p += __shfl_xor_sync(0xffffffffu, p, 4);
            p += __shfl_xor_sync(0xffffffffu, p, 2);
            p += __shfl_xor_sync(0xffffffffu, p, 1);

            const float s = p + __ldg(&bias[n]);   // uniform addr -> 1 transaction
            const float t = (float)((dirs >> d) & 1u);
            // numerically-stable BCE-with-logits
            acc += fmaxf(s, 0.0f) - s * t + log1pf(__expf(-fabsf(s)));
        }
    }

    // Deterministic block reduction (all lanes of a warp hold identical acc).
    __shared__ float sacc[WARPS_PER_BLOCK];
    if (lane == 0) sacc[threadIdx.x >> 5] = acc;
    __syncthreads();
    if (threadIdx.x == 0) {
        float s = 0.0f;
        #pragma unroll
        for (int i = 0; i < WARPS_PER_BLOCK; ++i) s += sacc[i];
        g_hs_partials[blockIdx.x] = s;
    }
}

__global__ void hs_reduce_kernel(float* __restrict__ out, int nblocks, float invB)
{
    __shared__ float s[256];
    float a = 0.0f;
    for (int i = threadIdx.x; i < nblocks; i += 256) a += g_hs_partials[i];
    s[threadIdx.x] = a;
    __syncthreads();
    #pragma unroll
    for (int ofs = 128; ofs > 0; ofs >>= 1) {
        if (threadIdx.x < ofs) s[threadIdx.x] += s[threadIdx.x + ofs];
        __syncthreads();
    }
    if (threadIdx.x == 0) out[0] = s[0] * invB;
}

extern "C" void kernel_launch(void* const* d_in, const int* in_sizes, int n_in,
                              void* d_out, int out_size)
{
    const float* emb      = (const float*)d_in[0];
    const int*   word_idx = (const int*)  d_in[1];
    const float4* W4      = (const float4*)d_in[2];
    const float* bias     = (const float*)d_in[3];
    float* out = (float*)d_out;

    const int B   = in_sizes[1];      // 16384
    const int Vm1 = in_sizes[3];      // V-1 = 131071

    int nblocks = (B + WARPS_PER_BLOCK - 1) / WARPS_PER_BLOCK;  // 2048
    if (nblocks > MAX_BLOCKS) nblocks = MAX_BLOCKS;  // shape contract: B<=65536

    hs_main_kernel<<<nblocks, WARPS_PER_BLOCK * 32>>>(emb, word_idx, W4, bias, B, Vm1);
    hs_reduce_kernel<<<1, 256>>>(out, nblocks, 1.0f / (float)B);
}

// round 4
// speedup vs baseline: 1.5561x; 1.5561x over previous
#include <cuda_runtime.h>
#include <cuda_bf16.h>

// HierarchicalSoftmax, fused single kernel.
//
// Inputs (metadata order):
//   d_in[0]: embeddings float32 [B, E]   (B=16384, E=128)
//   d_in[1]: word_idx   int32   [B]
//   d_in[2]: W          float32 [V-1, E] (V=131072)
//   d_in[3]: b          float32 [V-1]
// Output: float32 scalar = mean over B of sum over 17 path nodes of BCE.
//
// Layout: one warp per sample. Within a warp, the two 16-lane halves each
// handle one tree node per iteration (lane owns 8 embedding floats = 2 float4),
// so a node-pair costs 4 shfl_xor steps instead of 5 per node, and each LDG
// covers two contiguous 512B W rows (fully coalesced).

#define HS_D 17
#define TPB  256
#define WPB  8
#define MAX_BLOCKS 8192

__device__ float        g_hs_partials[MAX_BLOCKS];
__device__ unsigned int g_hs_count = 0;   // self-resetting ticket (wraps via atomicInc)

__global__ __launch_bounds__(TPB)
void hs_fused_kernel(const float*  __restrict__ emb,
                     const int*    __restrict__ word_idx,
                     const float4* __restrict__ W4,
                     const float*  __restrict__ bias,
                     float*        __restrict__ out,
                     int B, int Vm1, float invB)
{
    const int warp = blockIdx.x * WPB + (threadIdx.x >> 5);
    const int lane = threadIdx.x & 31;
    const int half = lane >> 4;       // which node of the pair this lane serves
    const int hl   = lane & 15;       // lane within the 16-lane group

    float acc = 0.0f;

    if (warp < B) {
        // Lane owns embedding elements [hl*8, hl*8+8): two float4s, coalesced.
        const float4* erow = reinterpret_cast<const float4*>(emb) + (size_t)warp * 32 + hl * 2;
        const float4 ea = erow[0];
        const float4 eb = erow[1];

        // Full leaf->root path precomputed so W-row loads are independent (MLP).
        int node = __ldg(&word_idx[warp]) + Vm1;
        int nodes[HS_D];
        unsigned dirs = 0u;
        #pragma unroll
        for (int d = 0; d < HS_D; ++d) {
            dirs |= (unsigned)(node & 1) << d;   // 1 iff came from left child
            node = (node - 1) >> 1;
            nodes[d] = node;
        }

        const int NP = (HS_D + 1) / 2;  // 9 pair-iterations (last pair half-valid)
        #pragma unroll
        for (int j = 0; j < NP; ++j) {
            const int  idx   = 2 * j + half;
            const bool valid = (idx < HS_D);
            const int  nidx  = valid ? idx : (HS_D - 1);
            const int  n     = nodes[nidx];

            // 16 lanes x 32B = one contiguous 512B W row per half-warp.
            const float4* wrow = W4 + (size_t)n * 32 + hl * 2;
            const float4 wa = __ldg(wrow);
            const float4 wb = __ldg(wrow + 1);

            float p = wa.x * ea.x + wa.y * ea.y + wa.z * ea.z + wa.w * ea.w
                    + wb.x * eb.x + wb.y * eb.y + wb.z * eb.z + wb.w * eb.w;

            // Butterfly within the 16-lane half (xor offsets < 16 stay in-half).
            p += __shfl_xor_sync(0xffffffffu, p, 8);
            p += __shfl_xor_sync(0xffffffffu, p, 4);
            p += __shfl_xor_sync(0xffffffffu, p, 2);
            p += __shfl_xor_sync(0xffffffffu, p, 1);

            const float s = p + __ldg(&bias[n]);
            const float t = (float)((dirs >> nidx) & 1u);
            // fast stable BCE-with-logits: max(s,0) - s*t + log(1+exp(-|s|))
            const float bce = fmaxf(s, 0.0f) - s * t + __logf(1.0f + __expf(-fabsf(s)));
            if (valid) acc += bce;
        }
        // Combine the two halves' accumulations (each half holds its own sum).
        acc += __shfl_xor_sync(0xffffffffu, acc, 16);
    }

    // ---- block reduction + last-block grid reduction (deterministic) ----
    __shared__ float sacc[WPB];
    __shared__ bool  is_last;
    if (lane == 0) sacc[threadIdx.x >> 5] = acc;
    __syncthreads();
    if (threadIdx.x == 0) {
        float s = 0.0f;
        #pragma unroll
        for (int i = 0; i < WPB; ++i) s += sacc[i];
        g_hs_partials[blockIdx.x] = s;
        __threadfence();
        // atomicInc wraps to 0 after gridDim.x-1 -> counter self-resets per launch.
        unsigned t = atomicInc(&g_hs_count, gridDim.x - 1);
        is_last = (t == gridDim.x - 1);
    }
    __syncthreads();

    if (is_last) {
        // Fixed-order strided + tree reduction: bit-identical every call.
        float a = 0.0f;
        for (int i = threadIdx.x; i < (int)gridDim.x; i += TPB)
            a += g_hs_partials[i];
        __shared__ float red[TPB];
        red[threadIdx.x] = a;
        __syncthreads();
        #pragma unroll
        for (int ofs = TPB / 2; ofs > 0; ofs >>= 1) {
            if (threadIdx.x < ofs) red[threadIdx.x] += red[threadIdx.x + ofs];
            __syncthreads();
        }
        if (threadIdx.x == 0) out[0] = red[0] * invB;
    }
}

extern "C" void kernel_launch(void* const* d_in, const int* in_sizes, int n_in,
                              void* d_out, int out_size)
{
    const float*  emb      = (const float*) d_in[0];
    const int*    word_idx = (const int*)   d_in[1];
    const float4* W4       = (const float4*)d_in[2];
    const float*  bias     = (const float*) d_in[3];
    float* out = (float*)d_out;

    const int B   = in_sizes[1];   // 16384
    const int Vm1 = in_sizes[3];   // V-1 = 131071

    int nblocks = (B + WPB - 1) / WPB;            // 2048
    if (nblocks > MAX_BLOCKS) nblocks = MAX_BLOCKS;

    hs_fused_kernel<<<nblocks, TPB>>>(emb, word_idx, W4, bias, out,
                                      B, Vm1, 1.0f / (float)B);
}